// round 2
// baseline (speedup 1.0000x reference)
#include <cuda_runtime.h>
#include <cstddef>

#define TILE_N 32
#define KC 32

typedef unsigned long long ull;

// -------- scratch (fixed problem sizes: N2=16384, N1=65536, Cout=64) --------
__device__ float g_y2t[16384 * 192];   // y2 transposed: [N2][C*3], 12.6 MB
__device__ int   g_idx[65536 * 3];     // global coarse row index per (fine,k)
__device__ float g_w  [65536 * 3];     // normalized inverse-dist weights

// ---------------- packed f32x2 helpers ----------------
__device__ __forceinline__ ull dup2(float x) {
    ull r;
    asm("mov.b64 %0, {%1, %1};" : "=l"(r) : "f"(x));
    return r;
}
__device__ __forceinline__ void ffma2(ull &c, ull a, ull b) {
    asm("fma.rn.f32x2 %0, %1, %2, %3;" : "=l"(c) : "l"(a), "l"(b), "l"(c));
}
__device__ __forceinline__ void unpack2(ull a, float &lo, float &hi) {
    asm("mov.b64 {%0, %1}, %2;" : "=f"(lo), "=f"(hi) : "l"(a));
}

union F4U { float4 f; ull u[2]; };

// ---------------------------------------------------------------------------
// kNN: 4 sub-threads per query. Each scans a strided quarter of the coarse
// segment with the half-metric m = 0.5|s|^2 - q.s (rank ~ d^2), tracking
// top-4. Merge across the 4 sub-lanes via shfl.xor, then re-rank merged
// top-4 by EXACT d^2 (matches reference selection except double-boundary
// coincidences) and keep the best 3.
// ---------------------------------------------------------------------------
__global__ __launch_bounds__(256)
void knn_kernel(const float* __restrict__ p1, const float* __restrict__ p2,
                int n1, int n2, int N1)
{
    __shared__ float4 sref[1024];
    const int tid = threadIdx.x;
    const int s = tid & 3;                    // sub-scan id
    const int q = blockIdx.x * 64 + (tid >> 2);
    const int batch = (blockIdx.x * 64) / n1; // 64 | n1
    const int base = batch * n2;

    const float qx = p1[3*q], qy = p1[3*q+1], qz = p1[3*q+2];

    float m0 = 3.4e38f, m1 = 3.4e38f, m2 = 3.4e38f, m3 = 3.4e38f;
    int i0 = 0, i1 = 0, i2 = 0, i3 = 0;

    for (int t0 = 0; t0 < n2; t0 += 1024) {
        __syncthreads();
        for (int j = tid; j < 1024; j += 256) {
            if (t0 + j < n2) {
                const float* sp = p2 + (size_t)3 * (base + t0 + j);
                float sx = sp[0], sy = sp[1], sz = sp[2];
                sref[j] = make_float4(sx, sy, sz, 0.5f*(sx*sx + sy*sy + sz*sz));
            }
        }
        __syncthreads();
#pragma unroll 4
        for (int t = 0; t < 256; t++) {
            float4 sv = sref[4*t + s];
            float m = fmaf(-qx, sv.x, fmaf(-qy, sv.y, fmaf(-qz, sv.z, sv.w)));
            if (m < m3) {
                int jj = t0 + 4*t + s;
                if (m < m2) {
                    m3 = m2; i3 = i2;
                    if (m < m1) {
                        m2 = m1; i2 = i1;
                        if (m < m0) { m1 = m0; i1 = i0; m0 = m; i0 = jj; }
                        else        { m1 = m;  i1 = jj; }
                    } else { m2 = m; i2 = jj; }
                } else { m3 = m; i3 = jj; }
            }
        }
    }

    // merge the 4 sub-lists (lanes s, s^1, s^2, s^3) via butterfly shuffles
#pragma unroll
    for (int delta = 1; delta <= 2; delta <<= 1) {
        float e0 = __shfl_xor_sync(~0u, m0, delta);
        float e1 = __shfl_xor_sync(~0u, m1, delta);
        float e2 = __shfl_xor_sync(~0u, m2, delta);
        float e3 = __shfl_xor_sync(~0u, m3, delta);
        int   j0 = __shfl_xor_sync(~0u, i0, delta);
        int   j1 = __shfl_xor_sync(~0u, i1, delta);
        int   j2 = __shfl_xor_sync(~0u, i2, delta);
        int   j3 = __shfl_xor_sync(~0u, i3, delta);
        float em[4] = { e0, e1, e2, e3 };
        int   ej[4] = { j0, j1, j2, j3 };
#pragma unroll
        for (int k = 0; k < 4; k++) {
            float m = em[k]; int jj = ej[k];
            if (m < m3) {
                if (m < m2) {
                    m3 = m2; i3 = i2;
                    if (m < m1) {
                        m2 = m1; i2 = i1;
                        if (m < m0) { m1 = m0; i1 = i0; m0 = m; i0 = jj; }
                        else        { m1 = m;  i1 = jj; }
                    } else { m2 = m; i2 = jj; }
                } else { m3 = m; i3 = jj; }
            }
        }
    }

    if (s == 0) {
        int id[4] = { i0, i1, i2, i3 };
        float d[4];
#pragma unroll
        for (int k = 0; k < 4; k++) {
            const float* sp = p2 + (size_t)3 * (base + id[k]);
            float dx = qx - sp[0], dy = qy - sp[1], dz = qz - sp[2];
            d[k] = fmaf(dz, dz, fmaf(dy, dy, dx*dx));   // exact, ref-matching
        }
        // stable ascending sort of 4 by exact d2
#pragma unroll
        for (int a = 0; a < 3; a++)
#pragma unroll
            for (int bb = 0; bb < 3 - a; bb++)
                if (d[bb] > d[bb+1]) {
                    float td = d[bb]; d[bb] = d[bb+1]; d[bb+1] = td;
                    int   ti = id[bb]; id[bb] = id[bb+1]; id[bb+1] = ti;
                }
        float w[3], wsum = 0.f;
#pragma unroll
        for (int k = 0; k < 3; k++) { w[k] = 1.f / (d[k] + 1e-8f); wsum += w[k]; }
        float inv = 1.f / wsum;
#pragma unroll
        for (int k = 0; k < 3; k++) {
            g_idx[q*3 + k] = base + id[k];
            g_w[q*3 + k]   = w[k] * inv;
        }
    }
}

// ---------------------------------------------------------------------------
// VN linear + leaky-ReLU with packed f32x2 math.
// Accumulator pair = (p, d) for one (o, point, comp): FFMA2 multiplies the
// packed weight pair (wf[o], wd[o]) by a duplicated x value.
// Weights staged in two smem arrays A (o%4 in {0,1}) / B (o%4 in {2,3}) as
// interleaved (wf, wd) floats so a single float4 read yields two packed pairs
// conflict-free.
// FUSE=false: writes y2 transposed to g_y2t[n][o*3+v]
// FUSE=true : adds 3-NN interpolation of g_y2t, writes out[(o*3+v)*N + n]
// ---------------------------------------------------------------------------
template<int CIN, bool FUSE>
__global__ __launch_bounds__(256, 2)
void vn_kernel(const float* __restrict__ x, const float* __restrict__ wfeat,
               const float* __restrict__ wdir, int N, float* __restrict__ out)
{
    __shared__ __align__(16) float swA[KC * 64];
    __shared__ __align__(16) float swB[KC * 64];
    __shared__ __align__(16) float xs [KC * 3 * TILE_N];
    __shared__ int   sidx[TILE_N * 3];
    __shared__ float swt [TILE_N * 3];

    const int tid = threadIdx.x;
    const int g = tid & 15;
    const int o_base = g * 4;
    const int pt_base = (tid >> 4) * 2;
    const int n0 = blockIdx.x * TILE_N;
    const int lane = tid & 31;
    const int wrow = tid >> 5;

    if (FUSE && tid < 96) {
        sidx[tid] = g_idx[n0*3 + tid];
        swt[tid]  = g_w[n0*3 + tid];
    }

    ull acc[24];
#pragma unroll
    for (int i = 0; i < 24; i++) acc[i] = 0ull;

    for (int c0 = 0; c0 < CIN; c0 += KC) {
        __syncthreads();
        // stage weights as interleaved (wf, wd) pairs
        for (int i = tid; i < 64 * KC; i += 256) {
            int o  = i >> 5;     // 0..63
            int cc = i & 31;
            float f = wfeat[o*CIN + c0 + cc];
            float d = wdir [o*CIN + c0 + cc];
            float* arr = ((o & 2) == 0) ? swA : swB;
            int pos = cc*64 + (o >> 2)*4 + (o & 1)*2;
            arr[pos]     = f;
            arr[pos + 1] = d;
        }
        // stage x tile: rows r = (c-c0)*3+v, cols = local point
        const float* xg = x + (size_t)(c0 * 3) * N + n0;
        for (int r = wrow; r < KC * 3; r += 8)
            xs[r * TILE_N + lane] = xg[(size_t)r * N + lane];
        __syncthreads();

#pragma unroll 4
        for (int cc = 0; cc < KC; ++cc) {
            F4U a4, b4;
            a4.f = *reinterpret_cast<const float4*>(&swA[cc*64 + g*4]);
            b4.f = *reinterpret_cast<const float4*>(&swB[cc*64 + g*4]);
            ull wp[4] = { a4.u[0], a4.u[1], b4.u[0], b4.u[1] };
            ull xd[6];
#pragma unroll
            for (int v = 0; v < 3; v++) {
                float2 xf = *reinterpret_cast<const float2*>(
                    &xs[(cc*3 + v)*TILE_N + pt_base]);
                xd[0*3 + v] = dup2(xf.x);
                xd[1*3 + v] = dup2(xf.y);
            }
#pragma unroll
            for (int i = 0; i < 4; i++)
#pragma unroll
                for (int k = 0; k < 2; k++)
#pragma unroll
                    for (int v = 0; v < 3; v++)
                        ffma2(acc[(i*2 + k)*3 + v], wp[i], xd[k*3 + v]);
        }
    }

    // unpack + VN leaky-ReLU into p[]
    float p[24];
#pragma unroll
    for (int i = 0; i < 4; i++)
#pragma unroll
        for (int k = 0; k < 2; k++) {
            const int sb = (i*2 + k) * 3;
            float px, dx, py, dy, pz, dz;
            unpack2(acc[sb + 0], px, dx);
            unpack2(acc[sb + 1], py, dy);
            unpack2(acc[sb + 2], pz, dz);
            float dot = px*dx + py*dy + pz*dz;
            if (dot < 0.f) {
                float d2 = dx*dx + dy*dy + dz*dz;
                float t = 0.8f * dot / (d2 + 1e-6f);
                px -= t*dx; py -= t*dy; pz -= t*dz;
            }
            p[sb + 0] = px; p[sb + 1] = py; p[sb + 2] = pz;
        }

    if (FUSE) {
        // add 3-NN interpolation from L2-resident g_y2t (contiguous 48B rows)
#pragma unroll
        for (int k = 0; k < 2; k++) {
            const int pt = pt_base + k;
#pragma unroll
            for (int kk = 0; kk < 3; kk++) {
                const int row = sidx[pt*3 + kk];
                const float w = swt[pt*3 + kk];
                const float4* src = reinterpret_cast<const float4*>(
                    g_y2t + (size_t)row * 192 + o_base * 3);
                float4 A = src[0], B = src[1], C = src[2];
                p[ 0 + 3*k + 0] += w * A.x;
                p[ 0 + 3*k + 1] += w * A.y;
                p[ 0 + 3*k + 2] += w * A.z;
                p[ 6 + 3*k + 0] += w * A.w;
                p[ 6 + 3*k + 1] += w * B.x;
                p[ 6 + 3*k + 2] += w * B.y;
                p[12 + 3*k + 0] += w * B.z;
                p[12 + 3*k + 1] += w * B.w;
                p[12 + 3*k + 2] += w * C.x;
                p[18 + 3*k + 0] += w * C.y;
                p[18 + 3*k + 1] += w * C.z;
                p[18 + 3*k + 2] += w * C.w;
            }
        }
#pragma unroll
        for (int i = 0; i < 4; i++)
#pragma unroll
            for (int k = 0; k < 2; k++)
#pragma unroll
                for (int v = 0; v < 3; v++)
                    out[(size_t)((o_base + i)*3 + v) * N + n0 + pt_base + k]
                        = p[(i*2 + k)*3 + v];
    } else {
#pragma unroll
        for (int k = 0; k < 2; k++) {
            float* dst = g_y2t + (size_t)(n0 + pt_base + k) * 192 + o_base * 3;
#pragma unroll
            for (int i = 0; i < 4; i++)
#pragma unroll
                for (int v = 0; v < 3; v++)
                    dst[i*3 + v] = p[(i*2 + k)*3 + v];
        }
    }
}

// ---------------------------------------------------------------------------
extern "C" void kernel_launch(void* const* d_in, const int* in_sizes, int n_in,
                              void* d_out, int out_size)
{
    (void)n_in; (void)out_size;
    const float* p1  = (const float*)d_in[0];
    const float* x1  = (const float*)d_in[1];
    const float* p2  = (const float*)d_in[3];
    const float* x2  = (const float*)d_in[4];
    const float* w1f = (const float*)d_in[6];
    const float* w1d = (const float*)d_in[7];
    const float* w2f = (const float*)d_in[8];
    const float* w2d = (const float*)d_in[9];

    const int b  = in_sizes[2];
    const int N1 = in_sizes[0] / 3;
    const int N2 = in_sizes[3] / 3;
    const int n1 = N1 / b;
    const int n2 = N2 / b;
    float* out = (float*)d_out;

    // 1) kNN (4 sub-threads per query)
    knn_kernel<<<N1 / 64, 256>>>(p1, p2, n1, n2, N1);

    // 2) vn2: x2 -> y2 transposed scratch  (Cin=128)
    vn_kernel<128, false><<<N2 / TILE_N, 256>>>(x2, w2f, w2d, N2, nullptr);

    // 3) vn1 + fused interpolation add -> out  (Cin=64)
    vn_kernel<64, true><<<N1 / TILE_N, 256>>>(x1, w1f, w1d, N1, out);
}

// round 3
// speedup vs baseline: 1.0768x; 1.0768x over previous
#include <cuda_runtime.h>
#include <cstddef>

#define TILE_N 32
#define KC 32

// -------- scratch (fixed problem sizes: N2=16384, N1=65536, Cout=64) --------
__device__ float g_y2t[16384 * 192];   // y2 transposed: [N2][C*3], 12.6 MB
__device__ int   g_idx[65536 * 3];     // global coarse row index per (fine,k)
__device__ float g_w  [65536 * 3];     // normalized inverse-dist weights

// ---------------------------------------------------------------------------
// kNN: 4 sub-threads per query, 2 queries per thread (one candidate LDS
// serves 2 tests). Half-metric m = 0.5|s|^2 - q.s for ranking; top-4 kept,
// merged across sub-lanes via shfl, then re-ranked by EXACT d^2 -> top-3.
// ---------------------------------------------------------------------------
#define KNN_INSERT(m, jj, h0, h1, h2, h3, j0, j1, j2, j3)                  \
    if ((m) < (h3)) {                                                      \
        if ((m) < (h2)) {                                                  \
            (h3) = (h2); (j3) = (j2);                                      \
            if ((m) < (h1)) {                                              \
                (h2) = (h1); (j2) = (j1);                                  \
                if ((m) < (h0)) { (h1) = (h0); (j1) = (j0);                \
                                  (h0) = (m);  (j0) = (jj); }              \
                else            { (h1) = (m);  (j1) = (jj); }              \
            } else { (h2) = (m); (j2) = (jj); }                            \
        } else { (h3) = (m); (j3) = (jj); }                                \
    }

__global__ __launch_bounds__(256)
void knn_kernel(const float* __restrict__ p1, const float* __restrict__ p2,
                int n1, int n2)
{
    __shared__ float4 sref[1024];
    const int tid = threadIdx.x;
    const int s = tid & 3;                     // sub-scan id
    const int q0 = blockIdx.x * 128 + (tid >> 2) * 2;
    const int q1 = q0 + 1;
    const int batch = (blockIdx.x * 128) / n1; // 128 | n1
    const int base = batch * n2;

    const float ax = p1[3*q0], ay = p1[3*q0+1], az = p1[3*q0+2];
    const float bx = p1[3*q1], by = p1[3*q1+1], bz = p1[3*q1+2];

    float a0 = 3.4e38f, a1 = 3.4e38f, a2 = 3.4e38f, a3 = 3.4e38f;
    float b0 = 3.4e38f, b1 = 3.4e38f, b2 = 3.4e38f, b3 = 3.4e38f;
    int ai0 = 0, ai1 = 0, ai2 = 0, ai3 = 0;
    int bi0 = 0, bi1 = 0, bi2 = 0, bi3 = 0;

    for (int t0 = 0; t0 < n2; t0 += 1024) {
        __syncthreads();
        for (int j = tid; j < 1024; j += 256) {
            if (t0 + j < n2) {
                const float* sp = p2 + (size_t)3 * (base + t0 + j);
                float sx = sp[0], sy = sp[1], sz = sp[2];
                sref[j] = make_float4(sx, sy, sz, 0.5f*(sx*sx + sy*sy + sz*sz));
            }
        }
        __syncthreads();
#pragma unroll 8
        for (int t = 0; t < 256; t++) {
            float4 sv = sref[4*t + s];
            int jj = t0 + 4*t + s;
            float ma = fmaf(-ax, sv.x, fmaf(-ay, sv.y, fmaf(-az, sv.z, sv.w)));
            float mb = fmaf(-bx, sv.x, fmaf(-by, sv.y, fmaf(-bz, sv.z, sv.w)));
            KNN_INSERT(ma, jj, a0, a1, a2, a3, ai0, ai1, ai2, ai3)
            KNN_INSERT(mb, jj, b0, b1, b2, b3, bi0, bi1, bi2, bi3)
        }
    }

    // merge the 4 sub-lists for both queries via butterfly shuffles
#pragma unroll
    for (int delta = 1; delta <= 2; delta <<= 1) {
        float em[8]; int ej[8];
        em[0] = __shfl_xor_sync(~0u, a0, delta); ej[0] = __shfl_xor_sync(~0u, ai0, delta);
        em[1] = __shfl_xor_sync(~0u, a1, delta); ej[1] = __shfl_xor_sync(~0u, ai1, delta);
        em[2] = __shfl_xor_sync(~0u, a2, delta); ej[2] = __shfl_xor_sync(~0u, ai2, delta);
        em[3] = __shfl_xor_sync(~0u, a3, delta); ej[3] = __shfl_xor_sync(~0u, ai3, delta);
        em[4] = __shfl_xor_sync(~0u, b0, delta); ej[4] = __shfl_xor_sync(~0u, bi0, delta);
        em[5] = __shfl_xor_sync(~0u, b1, delta); ej[5] = __shfl_xor_sync(~0u, bi1, delta);
        em[6] = __shfl_xor_sync(~0u, b2, delta); ej[6] = __shfl_xor_sync(~0u, bi2, delta);
        em[7] = __shfl_xor_sync(~0u, b3, delta); ej[7] = __shfl_xor_sync(~0u, bi3, delta);
#pragma unroll
        for (int k = 0; k < 4; k++) {
            KNN_INSERT(em[k], ej[k], a0, a1, a2, a3, ai0, ai1, ai2, ai3)
        }
#pragma unroll
        for (int k = 4; k < 8; k++) {
            KNN_INSERT(em[k], ej[k], b0, b1, b2, b3, bi0, bi1, bi2, bi3)
        }
    }

    if (s == 0) {
#pragma unroll
        for (int pass = 0; pass < 2; pass++) {
            const int q = pass ? q1 : q0;
            const float qx = pass ? bx : ax;
            const float qy = pass ? by : ay;
            const float qz = pass ? bz : az;
            int id[4];
            if (pass) { id[0]=bi0; id[1]=bi1; id[2]=bi2; id[3]=bi3; }
            else      { id[0]=ai0; id[1]=ai1; id[2]=ai2; id[3]=ai3; }
            float d[4];
#pragma unroll
            for (int k = 0; k < 4; k++) {
                const float* sp = p2 + (size_t)3 * (base + id[k]);
                float dx = qx - sp[0], dy = qy - sp[1], dz = qz - sp[2];
                d[k] = fmaf(dz, dz, fmaf(dy, dy, dx*dx));   // exact
            }
#pragma unroll
            for (int a = 0; a < 3; a++)
#pragma unroll
                for (int c = 0; c < 3 - a; c++)
                    if (d[c] > d[c+1]) {
                        float td = d[c]; d[c] = d[c+1]; d[c+1] = td;
                        int   ti = id[c]; id[c] = id[c+1]; id[c+1] = ti;
                    }
            float w[3], wsum = 0.f;
#pragma unroll
            for (int k = 0; k < 3; k++) { w[k] = 1.f / (d[k] + 1e-8f); wsum += w[k]; }
            float inv = 1.f / wsum;
#pragma unroll
            for (int k = 0; k < 3; k++) {
                g_idx[q*3 + k] = base + id[k];
                g_w[q*3 + k]   = w[k] * inv;
            }
        }
    }
}

// ---------------------------------------------------------------------------
// VN linear + leaky-ReLU (scalar FFMA; f32x2 is perf-neutral on sm_100a).
// Block: 256 threads, 32-point tile; thread = 4 outs x 2 pts x 3 comps,
// p and d accumulators. Weights staged transposed (stride 68, float4 reads).
// FUSE=false: y2 transposed to g_y2t[n][o*3+v]
// FUSE=true : += 3-NN interp of g_y2t, coalesced store via smem transpose.
// ---------------------------------------------------------------------------
template<int CIN, bool FUSE>
__global__ __launch_bounds__(256, 3)
void vn_kernel(const float* __restrict__ x, const float* __restrict__ wfeat,
               const float* __restrict__ wdir, int N, float* __restrict__ out)
{
    __shared__ __align__(16) float swf[KC * 68];
    __shared__ __align__(16) float swd[KC * 68];
    __shared__ __align__(16) float xs [96 * 33];   // >= KC*3*TILE_N; also transpose buf
    __shared__ int   sidx[TILE_N * 3];
    __shared__ float swt [TILE_N * 3];

    const int tid = threadIdx.x;
    const int g = tid & 15;
    const int o_base  = g * 4;
    const int pt_base = (tid >> 4) * 2;
    const int n0 = blockIdx.x * TILE_N;
    const int lane = tid & 31;
    const int wrow = tid >> 5;

    if (FUSE && tid < 96) {
        sidx[tid] = g_idx[n0*3 + tid];
        swt[tid]  = g_w[n0*3 + tid];
    }

    float p[24], q[24];
#pragma unroll
    for (int i = 0; i < 24; i++) { p[i] = 0.f; q[i] = 0.f; }

    for (int c0 = 0; c0 < CIN; c0 += KC) {
        __syncthreads();
        for (int i = tid; i < 64 * KC; i += 256) {
            int o  = i >> 5;
            int cc = i & 31;
            swf[cc*68 + o] = wfeat[o*CIN + c0 + cc];
            swd[cc*68 + o] = wdir [o*CIN + c0 + cc];
        }
        const float* xg = x + (size_t)(c0 * 3) * N + n0;
        for (int r = wrow; r < KC * 3; r += 8)
            xs[r * TILE_N + lane] = xg[(size_t)r * N + lane];
        __syncthreads();

#pragma unroll 8
        for (int cc = 0; cc < KC; ++cc) {
            const float4 f4 = *reinterpret_cast<const float4*>(&swf[cc*68 + o_base]);
            const float4 g4 = *reinterpret_cast<const float4*>(&swd[cc*68 + o_base]);
            const float2 xa = *reinterpret_cast<const float2*>(&xs[(cc*3+0)*TILE_N + pt_base]);
            const float2 xb = *reinterpret_cast<const float2*>(&xs[(cc*3+1)*TILE_N + pt_base]);
            const float2 xc = *reinterpret_cast<const float2*>(&xs[(cc*3+2)*TILE_N + pt_base]);
            float wf[4] = { f4.x, f4.y, f4.z, f4.w };
            float wg[4] = { g4.x, g4.y, g4.z, g4.w };
            float xv[2][3] = { { xa.x, xb.x, xc.x }, { xa.y, xb.y, xc.y } };
#pragma unroll
            for (int i = 0; i < 4; i++)
#pragma unroll
                for (int k = 0; k < 2; k++)
#pragma unroll
                    for (int v = 0; v < 3; v++) {
                        p[(i*2+k)*3+v] = fmaf(wf[i], xv[k][v], p[(i*2+k)*3+v]);
                        q[(i*2+k)*3+v] = fmaf(wg[i], xv[k][v], q[(i*2+k)*3+v]);
                    }
        }
    }

    // VN leaky-ReLU, in place into p
#pragma unroll
    for (int i = 0; i < 4; i++)
#pragma unroll
        for (int k = 0; k < 2; k++) {
            const int sb = (i*2 + k) * 3;
            float px = p[sb], py = p[sb+1], pz = p[sb+2];
            float dx = q[sb], dy = q[sb+1], dz = q[sb+2];
            float dot = px*dx + py*dy + pz*dz;
            if (dot < 0.f) {
                float d2 = dx*dx + dy*dy + dz*dz;
                float t = 0.8f * dot / (d2 + 1e-6f);
                p[sb]   = px - t*dx;
                p[sb+1] = py - t*dy;
                p[sb+2] = pz - t*dz;
            }
        }

    if (FUSE) {
        // add 3-NN interpolation from L2-resident g_y2t (contiguous 48B rows)
#pragma unroll
        for (int k = 0; k < 2; k++) {
            const int pt = pt_base + k;
#pragma unroll
            for (int kk = 0; kk < 3; kk++) {
                const int row = sidx[pt*3 + kk];
                const float w = swt[pt*3 + kk];
                const float4* src = reinterpret_cast<const float4*>(
                    g_y2t + (size_t)row * 192 + o_base * 3);
                float4 A = src[0], B = src[1], C = src[2];
                p[ 0 + 3*k + 0] += w * A.x;
                p[ 0 + 3*k + 1] += w * A.y;
                p[ 0 + 3*k + 2] += w * A.z;
                p[ 6 + 3*k + 0] += w * A.w;
                p[ 6 + 3*k + 1] += w * B.x;
                p[ 6 + 3*k + 2] += w * B.y;
                p[12 + 3*k + 0] += w * B.z;
                p[12 + 3*k + 1] += w * B.w;
                p[12 + 3*k + 2] += w * C.x;
                p[18 + 3*k + 0] += w * C.y;
                p[18 + 3*k + 1] += w * C.z;
                p[18 + 3*k + 2] += w * C.w;
            }
        }
        // coalesced store via smem transpose (two 96-row halves)
        __syncthreads();                       // done reading xs as x-tile
        if (g < 8) {
#pragma unroll
            for (int i = 0; i < 4; i++)
#pragma unroll
                for (int k = 0; k < 2; k++)
#pragma unroll
                    for (int v = 0; v < 3; v++)
                        xs[((o_base + i)*3 + v)*33 + pt_base + k] = p[(i*2+k)*3+v];
        }
        __syncthreads();
        for (int r = wrow; r < 96; r += 8)
            out[(size_t)r * N + n0 + lane] = xs[r*33 + lane];
        __syncthreads();
        if (g >= 8) {
#pragma unroll
            for (int i = 0; i < 4; i++)
#pragma unroll
                for (int k = 0; k < 2; k++)
#pragma unroll
                    for (int v = 0; v < 3; v++)
                        xs[((o_base + i)*3 + v - 96)*33 + pt_base + k] = p[(i*2+k)*3+v];
        }
        __syncthreads();
        for (int r = wrow; r < 96; r += 8)
            out[(size_t)(96 + r) * N + n0 + lane] = xs[r*33 + lane];
    } else {
#pragma unroll
        for (int k = 0; k < 2; k++) {
            float* dst = g_y2t + (size_t)(n0 + pt_base + k) * 192 + o_base * 3;
#pragma unroll
            for (int i = 0; i < 4; i++)
#pragma unroll
                for (int v = 0; v < 3; v++)
                    dst[i*3 + v] = p[(i*2+k)*3 + v];
        }
    }
}

// ---------------------------------------------------------------------------
extern "C" void kernel_launch(void* const* d_in, const int* in_sizes, int n_in,
                              void* d_out, int out_size)
{
    (void)n_in; (void)out_size;
    const float* p1  = (const float*)d_in[0];
    const float* x1  = (const float*)d_in[1];
    const float* p2  = (const float*)d_in[3];
    const float* x2  = (const float*)d_in[4];
    const float* w1f = (const float*)d_in[6];
    const float* w1d = (const float*)d_in[7];
    const float* w2f = (const float*)d_in[8];
    const float* w2d = (const float*)d_in[9];

    const int b  = in_sizes[2];
    const int N1 = in_sizes[0] / 3;
    const int N2 = in_sizes[3] / 3;
    const int n1 = N1 / b;
    const int n2 = N2 / b;
    float* out = (float*)d_out;

    // 1) kNN (4 sub-threads per query, 2 queries per thread)
    knn_kernel<<<N1 / 128, 256>>>(p1, p2, n1, n2);

    // 2) vn2: x2 -> y2 transposed scratch  (Cin=128)
    vn_kernel<128, false><<<N2 / TILE_N, 256>>>(x2, w2f, w2d, N2, nullptr);

    // 3) vn1 + fused interpolation add -> out  (Cin=64)
    vn_kernel<64, true><<<N1 / TILE_N, 256>>>(x1, w1f, w1d, N1, out);
}

// round 4
// speedup vs baseline: 1.4927x; 1.3862x over previous
#include <cuda_runtime.h>
#include <cstddef>

#define TILE_N 32
#define KC 32

#define GRID_R 8            // 8x8x8 cells per batch
#define NCELL 512
#define NB 4
#define CELL_H 0.125f

// -------- scratch (fixed problem sizes: N2=16384, N1=65536, Cout=64) --------
__device__ float g_y2t[16384 * 192];   // y2 transposed: [N2][C*3], 12.6 MB
__device__ int   g_idx[65536 * 3];     // global coarse row index per (fine,k)
__device__ float g_w  [65536 * 3];     // normalized inverse-dist weights

__device__ int    g_cnt[NB * NCELL];   // points per cell
__device__ int    g_off[NB * NCELL];   // exclusive offsets (within batch)
__device__ int    g_cur[NB * NCELL];   // scatter cursors
__device__ float4 g_pts[16384];        // cell-sorted points (x,y,z,bitcast row)

// ---------------------------------------------------------------------------
__device__ __forceinline__ int cell_of(float x, float y, float z) {
    int cx = min((int)(x * 8.0f), 7);
    int cy = min((int)(y * 8.0f), 7);
    int cz = min((int)(z * 8.0f), 7);
    return (cz << 6) + (cy << 3) + cx;
}

__global__ void zero_kernel() {
    int i = blockIdx.x * blockDim.x + threadIdx.x;
    if (i < NB * NCELL) g_cnt[i] = 0;
}

__global__ void pcount_kernel(const float* __restrict__ p2, int n2, int N2) {
    int i = blockIdx.x * blockDim.x + threadIdx.x;
    if (i >= N2) return;
    float x = p2[3*i], y = p2[3*i+1], z = p2[3*i+2];
    int batch = i / n2;
    atomicAdd(&g_cnt[batch * NCELL + cell_of(x, y, z)], 1);
}

// one block per batch: exclusive scan of 512 cell counts
__global__ __launch_bounds__(512)
void pscan_kernel() {
    __shared__ int sc[NCELL];
    int b = blockIdx.x, t = threadIdx.x;
    sc[t] = g_cnt[b * NCELL + t];
    __syncthreads();
    int v = sc[t];
#pragma unroll
    for (int d = 1; d < NCELL; d <<= 1) {
        int add = (t >= d) ? sc[t - d] : 0;
        __syncthreads();
        sc[t] = v = v + add;
        __syncthreads();
    }
    int excl = v - g_cnt[b * NCELL + t];
    g_off[b * NCELL + t] = excl;
    g_cur[b * NCELL + t] = excl;
}

__global__ void pscatter_kernel(const float* __restrict__ p2, int n2, int N2) {
    int i = blockIdx.x * blockDim.x + threadIdx.x;
    if (i >= N2) return;
    float x = p2[3*i], y = p2[3*i+1], z = p2[3*i+2];
    int batch = i / n2;
    int slot = atomicAdd(&g_cur[batch * NCELL + cell_of(x, y, z)], 1);
    g_pts[batch * n2 + slot] = make_float4(x, y, z, __int_as_float(i));
}

// ---------------------------------------------------------------------------
// grid kNN: 1 thread per query. Scan 27-cell neighborhood with exact d2,
// expand Chebyshev shells until d3 <= (R*h)^2 (provably exact top-3).
// ---------------------------------------------------------------------------
__global__ __launch_bounds__(256)
void knn_kernel(const float* __restrict__ p1, int n1, int n2, int N1)
{
    int q = blockIdx.x * blockDim.x + threadIdx.x;
    if (q >= N1) return;
    const float qx = p1[3*q], qy = p1[3*q+1], qz = p1[3*q+2];
    const int batch = q / n1;
    const int cbase = batch * NCELL;
    const int pbase = batch * n2;

    const int cx = min((int)(qx * 8.0f), 7);
    const int cy = min((int)(qy * 8.0f), 7);
    const int cz = min((int)(qz * 8.0f), 7);

    float e0 = 3.4e38f, e1 = 3.4e38f, e2 = 3.4e38f;
    int j0 = 0, j1 = 0, j2 = 0;

    for (int R = 1; R <= 8; R++) {
        const int zlo = max(cz - R, 0), zhi = min(cz + R, 7);
        const int ylo = max(cy - R, 0), yhi = min(cy + R, 7);
        const int xlo = max(cx - R, 0), xhi = min(cx + R, 7);
        for (int z = zlo; z <= zhi; z++) {
            int az = abs(z - cz);
            for (int y = ylo; y <= yhi; y++) {
                int ay = max(az, abs(y - cy));
                for (int x = xlo; x <= xhi; x++) {
                    int cd = max(ay, abs(x - cx));
                    // R==1: scan whole 3x3x3 box; R>1: only the new shell
                    if ((R == 1) ? (cd > 1) : (cd != R)) continue;
                    int c = cbase + (z << 6) + (y << 3) + x;
                    int s = g_off[c];
                    int e = s + g_cnt[c];
                    for (int t = s; t < e; t++) {
                        float4 pt = g_pts[pbase + t];
                        float dx = qx - pt.x, dy = qy - pt.y, dz = qz - pt.z;
                        float d2 = fmaf(dz, dz, fmaf(dy, dy, dx*dx));
                        if (d2 < e2) {
                            int jj = __float_as_int(pt.w);
                            if (d2 < e1) {
                                e2 = e1; j2 = j1;
                                if (d2 < e0) { e1 = e0; j1 = j0; e0 = d2; j0 = jj; }
                                else         { e1 = d2; j1 = jj; }
                            } else { e2 = d2; j2 = jj; }
                        }
                    }
                }
            }
        }
        float rad = (float)R * CELL_H;
        if (e2 <= 0.999f * rad * rad) break;
    }

    float w0 = 1.f / (e0 + 1e-8f);
    float w1 = 1.f / (e1 + 1e-8f);
    float w2 = 1.f / (e2 + 1e-8f);
    float inv = 1.f / (w0 + w1 + w2);
    g_idx[q*3 + 0] = j0;  g_w[q*3 + 0] = w0 * inv;
    g_idx[q*3 + 1] = j1;  g_w[q*3 + 1] = w1 * inv;
    g_idx[q*3 + 2] = j2;  g_w[q*3 + 2] = w2 * inv;
}

// ---------------------------------------------------------------------------
// VN linear + leaky-ReLU (unchanged from R3: scalar FFMA, 3 blocks/SM,
// coalesced fused epilogue).
// ---------------------------------------------------------------------------
template<int CIN, bool FUSE>
__global__ __launch_bounds__(256, 3)
void vn_kernel(const float* __restrict__ x, const float* __restrict__ wfeat,
               const float* __restrict__ wdir, int N, float* __restrict__ out)
{
    __shared__ __align__(16) float swf[KC * 68];
    __shared__ __align__(16) float swd[KC * 68];
    __shared__ __align__(16) float xs [96 * 33];
    __shared__ int   sidx[TILE_N * 3];
    __shared__ float swt [TILE_N * 3];

    const int tid = threadIdx.x;
    const int g = tid & 15;
    const int o_base  = g * 4;
    const int pt_base = (tid >> 4) * 2;
    const int n0 = blockIdx.x * TILE_N;
    const int lane = tid & 31;
    const int wrow = tid >> 5;

    if (FUSE && tid < 96) {
        sidx[tid] = g_idx[n0*3 + tid];
        swt[tid]  = g_w[n0*3 + tid];
    }

    float p[24], q[24];
#pragma unroll
    for (int i = 0; i < 24; i++) { p[i] = 0.f; q[i] = 0.f; }

    for (int c0 = 0; c0 < CIN; c0 += KC) {
        __syncthreads();
        for (int i = tid; i < 64 * KC; i += 256) {
            int o  = i >> 5;
            int cc = i & 31;
            swf[cc*68 + o] = wfeat[o*CIN + c0 + cc];
            swd[cc*68 + o] = wdir [o*CIN + c0 + cc];
        }
        const float* xg = x + (size_t)(c0 * 3) * N + n0;
        for (int r = wrow; r < KC * 3; r += 8)
            xs[r * TILE_N + lane] = xg[(size_t)r * N + lane];
        __syncthreads();

#pragma unroll 8
        for (int cc = 0; cc < KC; ++cc) {
            const float4 f4 = *reinterpret_cast<const float4*>(&swf[cc*68 + o_base]);
            const float4 g4 = *reinterpret_cast<const float4*>(&swd[cc*68 + o_base]);
            const float2 xa = *reinterpret_cast<const float2*>(&xs[(cc*3+0)*TILE_N + pt_base]);
            const float2 xb = *reinterpret_cast<const float2*>(&xs[(cc*3+1)*TILE_N + pt_base]);
            const float2 xc = *reinterpret_cast<const float2*>(&xs[(cc*3+2)*TILE_N + pt_base]);
            float wf[4] = { f4.x, f4.y, f4.z, f4.w };
            float wg[4] = { g4.x, g4.y, g4.z, g4.w };
            float xv[2][3] = { { xa.x, xb.x, xc.x }, { xa.y, xb.y, xc.y } };
#pragma unroll
            for (int i = 0; i < 4; i++)
#pragma unroll
                for (int k = 0; k < 2; k++)
#pragma unroll
                    for (int v = 0; v < 3; v++) {
                        p[(i*2+k)*3+v] = fmaf(wf[i], xv[k][v], p[(i*2+k)*3+v]);
                        q[(i*2+k)*3+v] = fmaf(wg[i], xv[k][v], q[(i*2+k)*3+v]);
                    }
        }
    }

#pragma unroll
    for (int i = 0; i < 4; i++)
#pragma unroll
        for (int k = 0; k < 2; k++) {
            const int sb = (i*2 + k) * 3;
            float px = p[sb], py = p[sb+1], pz = p[sb+2];
            float dx = q[sb], dy = q[sb+1], dz = q[sb+2];
            float dot = px*dx + py*dy + pz*dz;
            if (dot < 0.f) {
                float d2 = dx*dx + dy*dy + dz*dz;
                float t = 0.8f * dot / (d2 + 1e-6f);
                p[sb]   = px - t*dx;
                p[sb+1] = py - t*dy;
                p[sb+2] = pz - t*dz;
            }
        }

    if (FUSE) {
#pragma unroll
        for (int k = 0; k < 2; k++) {
            const int pt = pt_base + k;
#pragma unroll
            for (int kk = 0; kk < 3; kk++) {
                const int row = sidx[pt*3 + kk];
                const float w = swt[pt*3 + kk];
                const float4* src = reinterpret_cast<const float4*>(
                    g_y2t + (size_t)row * 192 + o_base * 3);
                float4 A = src[0], B = src[1], C = src[2];
                p[ 0 + 3*k + 0] += w * A.x;
                p[ 0 + 3*k + 1] += w * A.y;
                p[ 0 + 3*k + 2] += w * A.z;
                p[ 6 + 3*k + 0] += w * A.w;
                p[ 6 + 3*k + 1] += w * B.x;
                p[ 6 + 3*k + 2] += w * B.y;
                p[12 + 3*k + 0] += w * B.z;
                p[12 + 3*k + 1] += w * B.w;
                p[12 + 3*k + 2] += w * C.x;
                p[18 + 3*k + 0] += w * C.y;
                p[18 + 3*k + 1] += w * C.z;
                p[18 + 3*k + 2] += w * C.w;
            }
        }
        __syncthreads();
        if (g < 8) {
#pragma unroll
            for (int i = 0; i < 4; i++)
#pragma unroll
                for (int k = 0; k < 2; k++)
#pragma unroll
                    for (int v = 0; v < 3; v++)
                        xs[((o_base + i)*3 + v)*33 + pt_base + k] = p[(i*2+k)*3+v];
        }
        __syncthreads();
        for (int r = wrow; r < 96; r += 8)
            out[(size_t)r * N + n0 + lane] = xs[r*33 + lane];
        __syncthreads();
        if (g >= 8) {
#pragma unroll
            for (int i = 0; i < 4; i++)
#pragma unroll
                for (int k = 0; k < 2; k++)
#pragma unroll
                    for (int v = 0; v < 3; v++)
                        xs[((o_base + i)*3 + v - 96)*33 + pt_base + k] = p[(i*2+k)*3+v];
        }
        __syncthreads();
        for (int r = wrow; r < 96; r += 8)
            out[(size_t)(96 + r) * N + n0 + lane] = xs[r*33 + lane];
    } else {
#pragma unroll
        for (int k = 0; k < 2; k++) {
            float* dst = g_y2t + (size_t)(n0 + pt_base + k) * 192 + o_base * 3;
#pragma unroll
            for (int i = 0; i < 4; i++)
#pragma unroll
                for (int v = 0; v < 3; v++)
                    dst[i*3 + v] = p[(i*2+k)*3 + v];
        }
    }
}

// ---------------------------------------------------------------------------
extern "C" void kernel_launch(void* const* d_in, const int* in_sizes, int n_in,
                              void* d_out, int out_size)
{
    (void)n_in; (void)out_size;
    const float* p1  = (const float*)d_in[0];
    const float* x1  = (const float*)d_in[1];
    const float* p2  = (const float*)d_in[3];
    const float* x2  = (const float*)d_in[4];
    const float* w1f = (const float*)d_in[6];
    const float* w1d = (const float*)d_in[7];
    const float* w2f = (const float*)d_in[8];
    const float* w2d = (const float*)d_in[9];

    const int b  = in_sizes[2];
    const int N1 = in_sizes[0] / 3;
    const int N2 = in_sizes[3] / 3;
    const int n1 = N1 / b;
    const int n2 = N2 / b;
    float* out = (float*)d_out;

    // grid build + kNN
    zero_kernel<<<(NB*NCELL + 255)/256, 256>>>();
    pcount_kernel<<<(N2 + 255)/256, 256>>>(p2, n2, N2);
    pscan_kernel<<<NB, 512>>>();
    pscatter_kernel<<<(N2 + 255)/256, 256>>>(p2, n2, N2);
    knn_kernel<<<(N1 + 255)/256, 256>>>(p1, n1, n2, N1);

    // vn2: x2 -> y2 transposed scratch  (Cin=128)
    vn_kernel<128, false><<<N2 / TILE_N, 256>>>(x2, w2f, w2d, N2, nullptr);

    // vn1 + fused interpolation add -> out  (Cin=64)
    vn_kernel<64, true><<<N1 / TILE_N, 256>>>(x1, w1f, w1d, N1, out);
}

// round 5
// speedup vs baseline: 1.6288x; 1.0912x over previous
#include <cuda_runtime.h>
#include <cstddef>

#define TILE_N 32
#define KC 32

#define NCELL 512           // 8x8x8 cells per batch
#define NB 4
#define CELL_H 0.125f

// -------- scratch (fixed problem sizes: N2=16384, N1=65536, Cout=64) --------
__device__ float g_y2t[16384 * 192];   // y2 transposed: [N2][C*3], 12.6 MB
__device__ int   g_idx[65536 * 3];     // global coarse row index per (fine,k)
__device__ float g_w  [65536 * 3];     // normalized inverse-dist weights

// segment 0..NB-1: coarse-point grid; segment NB..2NB-1: query grid
__device__ int    g_cnt[2 * NB * NCELL];
__device__ int    g_off[2 * NB * NCELL];
__device__ int    g_cur[2 * NB * NCELL];
__device__ float4 g_pts [16384];       // cell-sorted coarse points (x,y,z,row)
__device__ float4 g_qpts[65536];       // cell-sorted queries (x,y,z,qidx)

// ---------------------------------------------------------------------------
__device__ __forceinline__ int cell_of(float x, float y, float z) {
    int cx = min((int)(x * 8.0f), 7);
    int cy = min((int)(y * 8.0f), 7);
    int cz = min((int)(z * 8.0f), 7);
    return (cz << 6) + (cy << 3) + cx;
}

__global__ void zero_kernel() {
    int i = blockIdx.x * blockDim.x + threadIdx.x;
    if (i < 2 * NB * NCELL) g_cnt[i] = 0;
}

// count both grids: grid.x covers N2 (points) then N1 (queries)
__global__ void count_kernel(const float* __restrict__ p2,
                             const float* __restrict__ p1,
                             int n2, int N2, int n1, int N1)
{
    int i = blockIdx.x * blockDim.x + threadIdx.x;
    if (i < N2) {
        float x = p2[3*i], y = p2[3*i+1], z = p2[3*i+2];
        atomicAdd(&g_cnt[(i / n2) * NCELL + cell_of(x, y, z)], 1);
    }
    int j = i - N2;
    if (j >= 0 && j < N1) {
        float x = p1[3*j], y = p1[3*j+1], z = p1[3*j+2];
        atomicAdd(&g_cnt[(NB + j / n1) * NCELL + cell_of(x, y, z)], 1);
    }
}

// one block per segment (2*NB blocks): exclusive scan of 512 cell counts
__global__ __launch_bounds__(512)
void scan_kernel() {
    __shared__ int sc[NCELL];
    int b = blockIdx.x, t = threadIdx.x;
    sc[t] = g_cnt[b * NCELL + t];
    __syncthreads();
    int v = sc[t];
#pragma unroll
    for (int d = 1; d < NCELL; d <<= 1) {
        int add = (t >= d) ? sc[t - d] : 0;
        __syncthreads();
        sc[t] = v = v + add;
        __syncthreads();
    }
    int excl = v - g_cnt[b * NCELL + t];
    g_off[b * NCELL + t] = excl;
    g_cur[b * NCELL + t] = excl;
}

__global__ void scatter_kernel(const float* __restrict__ p2,
                               const float* __restrict__ p1,
                               int n2, int N2, int n1, int N1)
{
    int i = blockIdx.x * blockDim.x + threadIdx.x;
    if (i < N2) {
        float x = p2[3*i], y = p2[3*i+1], z = p2[3*i+2];
        int batch = i / n2;
        int slot = atomicAdd(&g_cur[batch * NCELL + cell_of(x, y, z)], 1);
        g_pts[batch * n2 + slot] = make_float4(x, y, z, __int_as_float(i));
    }
    int j = i - N2;
    if (j >= 0 && j < N1) {
        float x = p1[3*j], y = p1[3*j+1], z = p1[3*j+2];
        int batch = j / n1;
        int slot = atomicAdd(&g_cur[(NB + batch) * NCELL + cell_of(x, y, z)], 1);
        g_qpts[batch * n1 + slot] = make_float4(x, y, z, __int_as_float(j));
    }
}

// ---------------------------------------------------------------------------
// grid kNN over CELL-SORTED queries: warp lanes share a cell -> uniform
// control flow + broadcast candidate loads. Exact d2, expanding Chebyshev
// shells; stop when d3 <= (R*h)^2 (provably exact top-3).
// ---------------------------------------------------------------------------
__global__ __launch_bounds__(256)
void knn_kernel(int n1, int n2, int N1)
{
    int i = blockIdx.x * blockDim.x + threadIdx.x;
    if (i >= N1) return;
    float4 qp = g_qpts[i];
    const float qx = qp.x, qy = qp.y, qz = qp.z;
    const int q = __float_as_int(qp.w);
    const int batch = i / n1;
    const int cbase = batch * NCELL;
    const int pbase = batch * n2;

    const int cx = min((int)(qx * 8.0f), 7);
    const int cy = min((int)(qy * 8.0f), 7);
    const int cz = min((int)(qz * 8.0f), 7);

    float e0 = 3.4e38f, e1 = 3.4e38f, e2 = 3.4e38f;
    int j0 = 0, j1 = 0, j2 = 0;

    for (int R = 1; R <= 8; R++) {
        const int zlo = max(cz - R, 0), zhi = min(cz + R, 7);
        const int ylo = max(cy - R, 0), yhi = min(cy + R, 7);
        const int xlo = max(cx - R, 0), xhi = min(cx + R, 7);
        for (int z = zlo; z <= zhi; z++) {
            int az = abs(z - cz);
            for (int y = ylo; y <= yhi; y++) {
                int ay = max(az, abs(y - cy));
                for (int x = xlo; x <= xhi; x++) {
                    int cd = max(ay, abs(x - cx));
                    if ((R == 1) ? (cd > 1) : (cd != R)) continue;
                    int c = cbase + (z << 6) + (y << 3) + x;
                    int s = g_off[c];
                    int e = s + g_cnt[c];
                    for (int t = s; t < e; t++) {
                        float4 pt = g_pts[pbase + t];
                        float dx = qx - pt.x, dy = qy - pt.y, dz = qz - pt.z;
                        float d2 = fmaf(dz, dz, fmaf(dy, dy, dx*dx));
                        if (d2 < e2) {
                            int jj = __float_as_int(pt.w);
                            if (d2 < e1) {
                                e2 = e1; j2 = j1;
                                if (d2 < e0) { e1 = e0; j1 = j0; e0 = d2; j0 = jj; }
                                else         { e1 = d2; j1 = jj; }
                            } else { e2 = d2; j2 = jj; }
                        }
                    }
                }
            }
        }
        float rad = (float)R * CELL_H;
        if (e2 <= 0.999f * rad * rad) break;
    }

    float w0 = 1.f / (e0 + 1e-8f);
    float w1 = 1.f / (e1 + 1e-8f);
    float w2 = 1.f / (e2 + 1e-8f);
    float inv = 1.f / (w0 + w1 + w2);
    g_idx[q*3 + 0] = j0;  g_w[q*3 + 0] = w0 * inv;
    g_idx[q*3 + 1] = j1;  g_w[q*3 + 1] = w1 * inv;
    g_idx[q*3 + 2] = j2;  g_w[q*3 + 2] = w2 * inv;
}

// ---------------------------------------------------------------------------
// VN linear + leaky-ReLU (unchanged: scalar FFMA, 3 blocks/SM, coalesced
// fused epilogue).
// ---------------------------------------------------------------------------
template<int CIN, bool FUSE>
__global__ __launch_bounds__(256, 3)
void vn_kernel(const float* __restrict__ x, const float* __restrict__ wfeat,
               const float* __restrict__ wdir, int N, float* __restrict__ out)
{
    __shared__ __align__(16) float swf[KC * 68];
    __shared__ __align__(16) float swd[KC * 68];
    __shared__ __align__(16) float xs [96 * 33];
    __shared__ int   sidx[TILE_N * 3];
    __shared__ float swt [TILE_N * 3];

    const int tid = threadIdx.x;
    const int g = tid & 15;
    const int o_base  = g * 4;
    const int pt_base = (tid >> 4) * 2;
    const int n0 = blockIdx.x * TILE_N;
    const int lane = tid & 31;
    const int wrow = tid >> 5;

    if (FUSE && tid < 96) {
        sidx[tid] = g_idx[n0*3 + tid];
        swt[tid]  = g_w[n0*3 + tid];
    }

    float p[24], q[24];
#pragma unroll
    for (int i = 0; i < 24; i++) { p[i] = 0.f; q[i] = 0.f; }

    for (int c0 = 0; c0 < CIN; c0 += KC) {
        __syncthreads();
        for (int i = tid; i < 64 * KC; i += 256) {
            int o  = i >> 5;
            int cc = i & 31;
            swf[cc*68 + o] = wfeat[o*CIN + c0 + cc];
            swd[cc*68 + o] = wdir [o*CIN + c0 + cc];
        }
        const float* xg = x + (size_t)(c0 * 3) * N + n0;
        for (int r = wrow; r < KC * 3; r += 8)
            xs[r * TILE_N + lane] = xg[(size_t)r * N + lane];
        __syncthreads();

#pragma unroll 8
        for (int cc = 0; cc < KC; ++cc) {
            const float4 f4 = *reinterpret_cast<const float4*>(&swf[cc*68 + o_base]);
            const float4 g4 = *reinterpret_cast<const float4*>(&swd[cc*68 + o_base]);
            const float2 xa = *reinterpret_cast<const float2*>(&xs[(cc*3+0)*TILE_N + pt_base]);
            const float2 xb = *reinterpret_cast<const float2*>(&xs[(cc*3+1)*TILE_N + pt_base]);
            const float2 xc = *reinterpret_cast<const float2*>(&xs[(cc*3+2)*TILE_N + pt_base]);
            float wf[4] = { f4.x, f4.y, f4.z, f4.w };
            float wg[4] = { g4.x, g4.y, g4.z, g4.w };
            float xv[2][3] = { { xa.x, xb.x, xc.x }, { xa.y, xb.y, xc.y } };
#pragma unroll
            for (int i = 0; i < 4; i++)
#pragma unroll
                for (int k = 0; k < 2; k++)
#pragma unroll
                    for (int v = 0; v < 3; v++) {
                        p[(i*2+k)*3+v] = fmaf(wf[i], xv[k][v], p[(i*2+k)*3+v]);
                        q[(i*2+k)*3+v] = fmaf(wg[i], xv[k][v], q[(i*2+k)*3+v]);
                    }
        }
    }

#pragma unroll
    for (int i = 0; i < 4; i++)
#pragma unroll
        for (int k = 0; k < 2; k++) {
            const int sb = (i*2 + k) * 3;
            float px = p[sb], py = p[sb+1], pz = p[sb+2];
            float dx = q[sb], dy = q[sb+1], dz = q[sb+2];
            float dot = px*dx + py*dy + pz*dz;
            if (dot < 0.f) {
                float d2 = dx*dx + dy*dy + dz*dz;
                float t = 0.8f * dot / (d2 + 1e-6f);
                p[sb]   = px - t*dx;
                p[sb+1] = py - t*dy;
                p[sb+2] = pz - t*dz;
            }
        }

    if (FUSE) {
#pragma unroll
        for (int k = 0; k < 2; k++) {
            const int pt = pt_base + k;
#pragma unroll
            for (int kk = 0; kk < 3; kk++) {
                const int row = sidx[pt*3 + kk];
                const float w = swt[pt*3 + kk];
                const float4* src = reinterpret_cast<const float4*>(
                    g_y2t + (size_t)row * 192 + o_base * 3);
                float4 A = src[0], B = src[1], C = src[2];
                p[ 0 + 3*k + 0] += w * A.x;
                p[ 0 + 3*k + 1] += w * A.y;
                p[ 0 + 3*k + 2] += w * A.z;
                p[ 6 + 3*k + 0] += w * A.w;
                p[ 6 + 3*k + 1] += w * B.x;
                p[ 6 + 3*k + 2] += w * B.y;
                p[12 + 3*k + 0] += w * B.z;
                p[12 + 3*k + 1] += w * B.w;
                p[12 + 3*k + 2] += w * C.x;
                p[18 + 3*k + 0] += w * C.y;
                p[18 + 3*k + 1] += w * C.z;
                p[18 + 3*k + 2] += w * C.w;
            }
        }
        __syncthreads();
        if (g < 8) {
#pragma unroll
            for (int i = 0; i < 4; i++)
#pragma unroll
                for (int k = 0; k < 2; k++)
#pragma unroll
                    for (int v = 0; v < 3; v++)
                        xs[((o_base + i)*3 + v)*33 + pt_base + k] = p[(i*2+k)*3+v];
        }
        __syncthreads();
        for (int r = wrow; r < 96; r += 8)
            out[(size_t)r * N + n0 + lane] = xs[r*33 + lane];
        __syncthreads();
        if (g >= 8) {
#pragma unroll
            for (int i = 0; i < 4; i++)
#pragma unroll
                for (int k = 0; k < 2; k++)
#pragma unroll
                    for (int v = 0; v < 3; v++)
                        xs[((o_base + i)*3 + v - 96)*33 + pt_base + k] = p[(i*2+k)*3+v];
        }
        __syncthreads();
        for (int r = wrow; r < 96; r += 8)
            out[(size_t)(96 + r) * N + n0 + lane] = xs[r*33 + lane];
    } else {
#pragma unroll
        for (int k = 0; k < 2; k++) {
            float* dst = g_y2t + (size_t)(n0 + pt_base + k) * 192 + o_base * 3;
#pragma unroll
            for (int i = 0; i < 4; i++)
#pragma unroll
                for (int v = 0; v < 3; v++)
                    dst[i*3 + v] = p[(i*2+k)*3 + v];
        }
    }
}

// ---------------------------------------------------------------------------
extern "C" void kernel_launch(void* const* d_in, const int* in_sizes, int n_in,
                              void* d_out, int out_size)
{
    (void)n_in; (void)out_size;
    const float* p1  = (const float*)d_in[0];
    const float* x1  = (const float*)d_in[1];
    const float* p2  = (const float*)d_in[3];
    const float* x2  = (const float*)d_in[4];
    const float* w1f = (const float*)d_in[6];
    const float* w1d = (const float*)d_in[7];
    const float* w2f = (const float*)d_in[8];
    const float* w2d = (const float*)d_in[9];

    const int b  = in_sizes[2];
    const int N1 = in_sizes[0] / 3;
    const int N2 = in_sizes[3] / 3;
    const int n1 = N1 / b;
    const int n2 = N2 / b;
    float* out = (float*)d_out;

    // grid build (points + queries) + cell-coherent kNN
    const int NT = N2 + N1;
    zero_kernel<<<(2*NB*NCELL + 255)/256, 256>>>();
    count_kernel<<<(NT + 255)/256, 256>>>(p2, p1, n2, N2, n1, N1);
    scan_kernel<<<2*NB, 512>>>();
    scatter_kernel<<<(NT + 255)/256, 256>>>(p2, p1, n2, N2, n1, N1);
    knn_kernel<<<(N1 + 255)/256, 256>>>(n1, n2, N1);

    // vn2: x2 -> y2 transposed scratch  (Cin=128)
    vn_kernel<128, false><<<N2 / TILE_N, 256>>>(x2, w2f, w2d, N2, nullptr);

    // vn1 + fused interpolation add -> out  (Cin=64)
    vn_kernel<64, true><<<N1 / TILE_N, 256>>>(x1, w1f, w1d, N1, out);
}

// round 6
// speedup vs baseline: 1.6418x; 1.0079x over previous
#include <cuda_runtime.h>
#include <cstddef>

#define TILE_N 32
#define KC 32

#define NCELL 512           // 8x8x8 cells per batch
#define NB 4
#define CELL_H 0.125f

// -------- scratch (fixed problem sizes: N2=16384, N1=65536, Cout=64) --------
__device__ float g_y2t[16384 * 192];   // y2 transposed: [N2][C*3], 12.6 MB
__device__ int   g_idx[65536 * 3];     // global coarse row index per (fine,k)
__device__ float g_w  [65536 * 3];     // normalized inverse-dist weights

// segment 0..NB-1: coarse-point grid; segment NB..2NB-1: query grid
__device__ int    g_cnt[2 * NB * NCELL];
__device__ int    g_off[2 * NB * NCELL];
__device__ int    g_cur[2 * NB * NCELL];
__device__ float4 g_pts [16384];       // cell-sorted coarse points (x,y,z,row)
__device__ float4 g_qpts[65536];       // cell-sorted queries (x,y,z,qidx)

// ---------------------------------------------------------------------------
__device__ __forceinline__ int cell_of(float x, float y, float z) {
    int cx = min((int)(x * 8.0f), 7);
    int cy = min((int)(y * 8.0f), 7);
    int cz = min((int)(z * 8.0f), 7);
    return (cz << 6) + (cy << 3) + cx;
}

__global__ void zero_kernel() {
    int i = blockIdx.x * blockDim.x + threadIdx.x;
    if (i < 2 * NB * NCELL) g_cnt[i] = 0;
}

// count both grids: grid.x covers N2 (points) then N1 (queries)
__global__ void count_kernel(const float* __restrict__ p2,
                             const float* __restrict__ p1,
                             int n2, int N2, int n1, int N1)
{
    int i = blockIdx.x * blockDim.x + threadIdx.x;
    if (i < N2) {
        float x = p2[3*i], y = p2[3*i+1], z = p2[3*i+2];
        atomicAdd(&g_cnt[(i / n2) * NCELL + cell_of(x, y, z)], 1);
    }
    int j = i - N2;
    if (j >= 0 && j < N1) {
        float x = p1[3*j], y = p1[3*j+1], z = p1[3*j+2];
        atomicAdd(&g_cnt[(NB + j / n1) * NCELL + cell_of(x, y, z)], 1);
    }
}

// one block per segment (2*NB blocks): exclusive scan of 512 cell counts
__global__ __launch_bounds__(512)
void scan_kernel() {
    __shared__ int sc[NCELL];
    int b = blockIdx.x, t = threadIdx.x;
    sc[t] = g_cnt[b * NCELL + t];
    __syncthreads();
    int v = sc[t];
#pragma unroll
    for (int d = 1; d < NCELL; d <<= 1) {
        int add = (t >= d) ? sc[t - d] : 0;
        __syncthreads();
        sc[t] = v = v + add;
        __syncthreads();
    }
    int excl = v - g_cnt[b * NCELL + t];
    g_off[b * NCELL + t] = excl;
    g_cur[b * NCELL + t] = excl;
}

__global__ void scatter_kernel(const float* __restrict__ p2,
                               const float* __restrict__ p1,
                               int n2, int N2, int n1, int N1)
{
    int i = blockIdx.x * blockDim.x + threadIdx.x;
    if (i < N2) {
        float x = p2[3*i], y = p2[3*i+1], z = p2[3*i+2];
        int batch = i / n2;
        int slot = atomicAdd(&g_cur[batch * NCELL + cell_of(x, y, z)], 1);
        g_pts[batch * n2 + slot] = make_float4(x, y, z, __int_as_float(i));
    }
    int j = i - N2;
    if (j >= 0 && j < N1) {
        float x = p1[3*j], y = p1[3*j+1], z = p1[3*j+2];
        int batch = j / n1;
        int slot = atomicAdd(&g_cur[(NB + batch) * NCELL + cell_of(x, y, z)], 1);
        g_qpts[batch * n1 + slot] = make_float4(x, y, z, __int_as_float(j));
    }
}

// ---------------------------------------------------------------------------
// grid kNN over CELL-SORTED queries: warp lanes share a cell -> uniform
// control flow + broadcast candidate loads. Exact d2, expanding Chebyshev
// shells; stop when d3 <= (R*h)^2 (provably exact top-3).
// ---------------------------------------------------------------------------
__global__ __launch_bounds__(256)
void knn_kernel(int n1, int n2, int N1)
{
    int i = blockIdx.x * blockDim.x + threadIdx.x;
    if (i >= N1) return;
    float4 qp = g_qpts[i];
    const float qx = qp.x, qy = qp.y, qz = qp.z;
    const int q = __float_as_int(qp.w);
    const int batch = i / n1;
    const int cbase = batch * NCELL;
    const int pbase = batch * n2;

    const int cx = min((int)(qx * 8.0f), 7);
    const int cy = min((int)(qy * 8.0f), 7);
    const int cz = min((int)(qz * 8.0f), 7);

    float e0 = 3.4e38f, e1 = 3.4e38f, e2 = 3.4e38f;
    int j0 = 0, j1 = 0, j2 = 0;

    for (int R = 1; R <= 8; R++) {
        const int zlo = max(cz - R, 0), zhi = min(cz + R, 7);
        const int ylo = max(cy - R, 0), yhi = min(cy + R, 7);
        const int xlo = max(cx - R, 0), xhi = min(cx + R, 7);
        for (int z = zlo; z <= zhi; z++) {
            int az = abs(z - cz);
            for (int y = ylo; y <= yhi; y++) {
                int ay = max(az, abs(y - cy));
                for (int x = xlo; x <= xhi; x++) {
                    int cd = max(ay, abs(x - cx));
                    if ((R == 1) ? (cd > 1) : (cd != R)) continue;
                    int c = cbase + (z << 6) + (y << 3) + x;
                    int s = g_off[c];
                    int e = s + g_cnt[c];
                    for (int t = s; t < e; t++) {
                        float4 pt = g_pts[pbase + t];
                        float dx = qx - pt.x, dy = qy - pt.y, dz = qz - pt.z;
                        float d2 = fmaf(dz, dz, fmaf(dy, dy, dx*dx));
                        if (d2 < e2) {
                            int jj = __float_as_int(pt.w);
                            if (d2 < e1) {
                                e2 = e1; j2 = j1;
                                if (d2 < e0) { e1 = e0; j1 = j0; e0 = d2; j0 = jj; }
                                else         { e1 = d2; j1 = jj; }
                            } else { e2 = d2; j2 = jj; }
                        }
                    }
                }
            }
        }
        float rad = (float)R * CELL_H;
        if (e2 <= 0.999f * rad * rad) break;
    }

    float w0 = 1.f / (e0 + 1e-8f);
    float w1 = 1.f / (e1 + 1e-8f);
    float w2 = 1.f / (e2 + 1e-8f);
    float inv = 1.f / (w0 + w1 + w2);
    g_idx[q*3 + 0] = j0;  g_w[q*3 + 0] = w0 * inv;
    g_idx[q*3 + 1] = j1;  g_w[q*3 + 1] = w1 * inv;
    g_idx[q*3 + 2] = j2;  g_w[q*3 + 2] = w2 * inv;
}

// ---------------------------------------------------------------------------
// VN linear + leaky-ReLU (unchanged: scalar FFMA, 3 blocks/SM, coalesced
// fused epilogue).
// ---------------------------------------------------------------------------
template<int CIN, bool FUSE>
__global__ __launch_bounds__(256, 3)
void vn_kernel(const float* __restrict__ x, const float* __restrict__ wfeat,
               const float* __restrict__ wdir, int N, float* __restrict__ out)
{
    __shared__ __align__(16) float swf[KC * 68];
    __shared__ __align__(16) float swd[KC * 68];
    __shared__ __align__(16) float xs [96 * 33];
    __shared__ int   sidx[TILE_N * 3];
    __shared__ float swt [TILE_N * 3];

    const int tid = threadIdx.x;
    const int g = tid & 15;
    const int o_base  = g * 4;
    const int pt_base = (tid >> 4) * 2;
    const int n0 = blockIdx.x * TILE_N;
    const int lane = tid & 31;
    const int wrow = tid >> 5;

    if (FUSE && tid < 96) {
        sidx[tid] = g_idx[n0*3 + tid];
        swt[tid]  = g_w[n0*3 + tid];
    }

    float p[24], q[24];
#pragma unroll
    for (int i = 0; i < 24; i++) { p[i] = 0.f; q[i] = 0.f; }

    for (int c0 = 0; c0 < CIN; c0 += KC) {
        __syncthreads();
        for (int i = tid; i < 64 * KC; i += 256) {
            int o  = i >> 5;
            int cc = i & 31;
            swf[cc*68 + o] = wfeat[o*CIN + c0 + cc];
            swd[cc*68 + o] = wdir [o*CIN + c0 + cc];
        }
        const float* xg = x + (size_t)(c0 * 3) * N + n0;
        for (int r = wrow; r < KC * 3; r += 8)
            xs[r * TILE_N + lane] = xg[(size_t)r * N + lane];
        __syncthreads();

#pragma unroll 8
        for (int cc = 0; cc < KC; ++cc) {
            const float4 f4 = *reinterpret_cast<const float4*>(&swf[cc*68 + o_base]);
            const float4 g4 = *reinterpret_cast<const float4*>(&swd[cc*68 + o_base]);
            const float2 xa = *reinterpret_cast<const float2*>(&xs[(cc*3+0)*TILE_N + pt_base]);
            const float2 xb = *reinterpret_cast<const float2*>(&xs[(cc*3+1)*TILE_N + pt_base]);
            const float2 xc = *reinterpret_cast<const float2*>(&xs[(cc*3+2)*TILE_N + pt_base]);
            float wf[4] = { f4.x, f4.y, f4.z, f4.w };
            float wg[4] = { g4.x, g4.y, g4.z, g4.w };
            float xv[2][3] = { { xa.x, xb.x, xc.x }, { xa.y, xb.y, xc.y } };
#pragma unroll
            for (int i = 0; i < 4; i++)
#pragma unroll
                for (int k = 0; k < 2; k++)
#pragma unroll
                    for (int v = 0; v < 3; v++) {
                        p[(i*2+k)*3+v] = fmaf(wf[i], xv[k][v], p[(i*2+k)*3+v]);
                        q[(i*2+k)*3+v] = fmaf(wg[i], xv[k][v], q[(i*2+k)*3+v]);
                    }
        }
    }

#pragma unroll
    for (int i = 0; i < 4; i++)
#pragma unroll
        for (int k = 0; k < 2; k++) {
            const int sb = (i*2 + k) * 3;
            float px = p[sb], py = p[sb+1], pz = p[sb+2];
            float dx = q[sb], dy = q[sb+1], dz = q[sb+2];
            float dot = px*dx + py*dy + pz*dz;
            if (dot < 0.f) {
                float d2 = dx*dx + dy*dy + dz*dz;
                float t = 0.8f * dot / (d2 + 1e-6f);
                p[sb]   = px - t*dx;
                p[sb+1] = py - t*dy;
                p[sb+2] = pz - t*dz;
            }
        }

    if (FUSE) {
#pragma unroll
        for (int k = 0; k < 2; k++) {
            const int pt = pt_base + k;
#pragma unroll
            for (int kk = 0; kk < 3; kk++) {
                const int row = sidx[pt*3 + kk];
                const float w = swt[pt*3 + kk];
                const float4* src = reinterpret_cast<const float4*>(
                    g_y2t + (size_t)row * 192 + o_base * 3);
                float4 A = src[0], B = src[1], C = src[2];
                p[ 0 + 3*k + 0] += w * A.x;
                p[ 0 + 3*k + 1] += w * A.y;
                p[ 0 + 3*k + 2] += w * A.z;
                p[ 6 + 3*k + 0] += w * A.w;
                p[ 6 + 3*k + 1] += w * B.x;
                p[ 6 + 3*k + 2] += w * B.y;
                p[12 + 3*k + 0] += w * B.z;
                p[12 + 3*k + 1] += w * B.w;
                p[12 + 3*k + 2] += w * C.x;
                p[18 + 3*k + 0] += w * C.y;
                p[18 + 3*k + 1] += w * C.z;
                p[18 + 3*k + 2] += w * C.w;
            }
        }
        __syncthreads();
        if (g < 8) {
#pragma unroll
            for (int i = 0; i < 4; i++)
#pragma unroll
                for (int k = 0; k < 2; k++)
#pragma unroll
                    for (int v = 0; v < 3; v++)
                        xs[((o_base + i)*3 + v)*33 + pt_base + k] = p[(i*2+k)*3+v];
        }
        __syncthreads();
        for (int r = wrow; r < 96; r += 8)
            out[(size_t)r * N + n0 + lane] = xs[r*33 + lane];
        __syncthreads();
        if (g >= 8) {
#pragma unroll
            for (int i = 0; i < 4; i++)
#pragma unroll
                for (int k = 0; k < 2; k++)
#pragma unroll
                    for (int v = 0; v < 3; v++)
                        xs[((o_base + i)*3 + v - 96)*33 + pt_base + k] = p[(i*2+k)*3+v];
        }
        __syncthreads();
        for (int r = wrow; r < 96; r += 8)
            out[(size_t)(96 + r) * N + n0 + lane] = xs[r*33 + lane];
    } else {
#pragma unroll
        for (int k = 0; k < 2; k++) {
            float* dst = g_y2t + (size_t)(n0 + pt_base + k) * 192 + o_base * 3;
#pragma unroll
            for (int i = 0; i < 4; i++)
#pragma unroll
                for (int v = 0; v < 3; v++)
                    dst[i*3 + v] = p[(i*2+k)*3 + v];
        }
    }
}

// ---------------------------------------------------------------------------
extern "C" void kernel_launch(void* const* d_in, const int* in_sizes, int n_in,
                              void* d_out, int out_size)
{
    (void)n_in; (void)out_size;
    const float* p1  = (const float*)d_in[0];
    const float* x1  = (const float*)d_in[1];
    const float* p2  = (const float*)d_in[3];
    const float* x2  = (const float*)d_in[4];
    const float* w1f = (const float*)d_in[6];
    const float* w1d = (const float*)d_in[7];
    const float* w2f = (const float*)d_in[8];
    const float* w2d = (const float*)d_in[9];

    const int b  = in_sizes[2];
    const int N1 = in_sizes[0] / 3;
    const int N2 = in_sizes[3] / 3;
    const int n1 = N1 / b;
    const int n2 = N2 / b;
    float* out = (float*)d_out;

    // grid build (points + queries) + cell-coherent kNN
    const int NT = N2 + N1;
    zero_kernel<<<(2*NB*NCELL + 255)/256, 256>>>();
    count_kernel<<<(NT + 255)/256, 256>>>(p2, p1, n2, N2, n1, N1);
    scan_kernel<<<2*NB, 512>>>();
    scatter_kernel<<<(NT + 255)/256, 256>>>(p2, p1, n2, N2, n1, N1);
    knn_kernel<<<(N1 + 255)/256, 256>>>(n1, n2, N1);

    // vn2: x2 -> y2 transposed scratch  (Cin=128)
    vn_kernel<128, false><<<N2 / TILE_N, 256>>>(x2, w2f, w2d, N2, nullptr);

    // vn1 + fused interpolation add -> out  (Cin=64)
    vn_kernel<64, true><<<N1 / TILE_N, 256>>>(x1, w1f, w1d, N1, out);
}